// round 7
// baseline (speedup 1.0000x reference)
#include <cuda_runtime.h>
#include <math.h>

#define BGR 32768
#define NPG 54
#define EPG 144
#define GLOB 10
#define F0 8
#define F1 16
#define F2 4
#define CAT 226   /* 54*4 + 10 */
#define H1 128
#define BM 64

typedef unsigned long long u64;

// packed f32x2 helpers (Blackwell FFMA2 path)
__device__ __forceinline__ u64 pk2(float x, float y) {
    u64 r; asm("mov.b64 %0, {%1, %2};" : "=l"(r) : "f"(x), "f"(y)); return r;
}
__device__ __forceinline__ u64 ffma2(u64 a, u64 b, u64 c) {
    u64 d; asm("fma.rn.f32x2 %0, %1, %2, %3;" : "=l"(d) : "l"(a), "l"(b), "l"(c));
    return d;
}
__device__ __forceinline__ float2 up2(u64 v) {
    float x, y; asm("mov.b64 {%0, %1}, %2;" : "=f"(x), "=f"(y) : "l"(v));
    return make_float2(x, y);
}

// Scratch: concat([embeds, g]) per graph, [B, 226]
__device__ float g_emb[BGR * CAT];

// ---------------------------------------------------------------------------
// Kernel 1: per-graph GraphConv x2 (+ ReLU) and the global-feature MLP.
// One CTA (128 threads) per graph. Counting-sort CSR built once (warp-scan
// prefix sum), reused by both conv layers. All feature traffic is float4;
// FFMA2 on input-pairs in the linear layers (pairs free from float4 smem).
// ---------------------------------------------------------------------------
__global__ void __launch_bounds__(128) gconv_kernel(
    const float* __restrict__ x,
    const int*   __restrict__ eidx,    // [2, E]
    const float* __restrict__ eattr,
    const float* __restrict__ gfeat,
    const float* __restrict__ W_rel1, const float* __restrict__ b1,
    const float* __restrict__ W_root1,
    const float* __restrict__ W_rel2, const float* __restrict__ b2,
    const float* __restrict__ W_root2,
    const float* __restrict__ Wg1, const float* __restrict__ bg1,
    const float* __restrict__ Wg2, const float* __restrict__ bg2,
    const float* __restrict__ Wg3, const float* __restrict__ bg3)
{
    const int b   = blockIdx.x;
    const int tid = threadIdx.x;

    __shared__ float4 sx4[NPG * 2];       // x       [54][8]  as float4 pairs
    __shared__ float4 sh4[NPG * 4];       // conv1 out [54][16]
    __shared__ float4 sagg4[NPG * 4];     // agg scratch [54][16] (aliased early)
    __shared__ float2 sedge[EPG];         // dst-sorted {attr, src_as_float}
    __shared__ int    soff[NPG + 1];
    __shared__ int    scur[NPG];
    __shared__ int    wsum0;
    __shared__ float  wr1[F0 * F1], wrt1[F0 * F1], sb1[F1];
    __shared__ float  wr2[F1 * F2], wrt2[F1 * F2], sb2[F2];
    __shared__ float  wg1[GLOB * 8], wg2[64], wg3[80];
    __shared__ float  sbg1[8], sbg2[8], sbg3[GLOB], sgf[GLOB], sg1[8], sg2[8];

    // unsorted edge staging aliases sagg4 (unused until after scatter)
    float* sattr_u = (float*)sagg4;            // [144]
    short* ssrc_u  = (short*)(sattr_u + EPG);  // [144]
    short* sdst_u  = ssrc_u + EPG;             // [144]
    float* shf     = (float*)sh4;

    // ---- loads ----
    {
        const float4* xg = (const float4*)(x + (size_t)b * (NPG * F0));
        if (tid < NPG * 2) sx4[tid] = xg[tid];
    }
    {
        const int*   srcg = eidx + (size_t)b * EPG;
        const int*   dstg = eidx + (size_t)BGR * EPG + (size_t)b * EPG;
        const float* ag   = eattr + (size_t)b * EPG;
        const int base = b * NPG;
        for (int e = tid; e < EPG; e += 128) {
            ssrc_u[e]  = (short)(srcg[e] - base);
            sdst_u[e]  = (short)(dstg[e] - base);
            sattr_u[e] = ag[e];
        }
    }
    for (int i = tid; i < F0 * F1; i += 128) { wr1[i] = W_rel1[i]; wrt1[i] = W_root1[i]; }
    if (tid < F1 * F2) { wr2[tid] = W_rel2[tid]; wrt2[tid] = W_root2[tid]; }
    if (tid < F1) sb1[tid] = b1[tid];
    if (tid < F2) sb2[tid] = b2[tid];
    if (tid < GLOB * 8) wg1[tid] = Wg1[tid];
    if (tid < 64) wg2[tid] = Wg2[tid];
    if (tid < 80) wg3[tid] = Wg3[tid];
    if (tid < 8)  { sbg1[tid] = bg1[tid]; sbg2[tid] = bg2[tid]; }
    if (tid < GLOB) { sbg3[tid] = bg3[tid]; sgf[tid] = gfeat[(size_t)b * GLOB + tid]; }
    if (tid < NPG) scur[tid] = 0;
    __syncthreads();

    // ---- degree counts (+ global-MLP layer 1) ----
    for (int e = tid; e < EPG; e += 128) atomicAdd(&scur[sdst_u[e]], 1);
    if (tid < 8) {
        float v = sbg1[tid];
        #pragma unroll
        for (int i = 0; i < GLOB; i++) v += sgf[i] * wg1[i * 8 + tid];
        sg1[tid] = fmaxf(v, 0.f);
    }
    __syncthreads();

    // ---- warp-shuffle prefix scan over 54 counts (2 warps) ----
    if (tid < 64) {
        int c = (tid < NPG) ? scur[tid] : 0;
        int lane = tid & 31;
        int v = c;
        #pragma unroll
        for (int o = 1; o < 32; o <<= 1) {
            int u = __shfl_up_sync(0xffffffffu, v, o);
            if (lane >= o) v += u;
        }
        if (tid < NPG) soff[tid + 1] = v;
        if (tid == 31) wsum0 = v;
        if (tid == 0)  soff[0] = 0;
    }
    if (tid >= 64 && tid < 72) {   // global-MLP layer 2 on warp 2
        int j = tid - 64;
        float v = sbg2[j];
        #pragma unroll
        for (int i = 0; i < 8; i++) v += sg1[i] * wg2[i * 8 + j];
        sg2[j] = fmaxf(v, 0.f);
    }
    __syncthreads();
    if (tid >= 32 && tid < NPG) soff[tid + 1] += wsum0;
    __syncthreads();
    if (tid < NPG) scur[tid] = soff[tid];
    __syncthreads();

    // ---- scatter edges into CSR slots (+ global-MLP layer 3 writeout) ----
    for (int e = tid; e < EPG; e += 128) {
        int slot = atomicAdd(&scur[sdst_u[e]], 1);
        float2 pe; pe.x = sattr_u[e]; pe.y = __int_as_float((int)ssrc_u[e]);
        sedge[slot] = pe;
    }
    if (tid < GLOB) {
        float v = sbg3[tid];
        #pragma unroll
        for (int i = 0; i < 8; i++) v += sg2[i] * wg3[i * GLOB + tid];
        g_emb[(size_t)b * CAT + NPG * F2 + tid] = fmaxf(v, 0.f);
    }
    __syncthreads();   // sagg4 alias region dead after this -> reusable

    // ---- conv1 aggregation: one thread per (node, float4-half), FFMA2 ----
    if (tid < NPG * 2) {
        int n = tid >> 1, h = tid & 1;
        u64 acc0 = 0ULL, acc1 = 0ULL;
        int k1 = soff[n + 1];
        for (int k = soff[n]; k < k1; k++) {
            float2 e = sedge[k];
            u64 es = pk2(e.x, e.x);
            ulonglong2 xv = *(const ulonglong2*)&sx4[__float_as_int(e.y) * 2 + h];
            acc0 = ffma2(es, xv.x, acc0);
            acc1 = ffma2(es, xv.y, acc1);
        }
        float2 a01 = up2(acc0), a23 = up2(acc1);
        sagg4[tid] = make_float4(a01.x, a01.y, a23.x, a23.y);   // layout [n][2]
    }
    __syncthreads();

    // ---- conv1 linear + ReLU: input-pair FFMA2, weights packed in regs ----
    {
        const int j = tid & 15, g = tid >> 4;   // g in 0..7
        u64 wa[4], wb[4];
        #pragma unroll
        for (int i2 = 0; i2 < 4; i2++) {
            wa[i2] = pk2(wr1[(2 * i2) * F1 + j],  wr1[(2 * i2 + 1) * F1 + j]);
            wb[i2] = pk2(wrt1[(2 * i2) * F1 + j], wrt1[(2 * i2 + 1) * F1 + j]);
        }
        const float bj = sb1[j];
        for (int n = g; n < NPG; n += 8) {
            ulonglong2 a0 = *(const ulonglong2*)&sagg4[n * 2];
            ulonglong2 a1 = *(const ulonglong2*)&sagg4[n * 2 + 1];
            ulonglong2 x0 = *(const ulonglong2*)&sx4[n * 2];
            ulonglong2 x1 = *(const ulonglong2*)&sx4[n * 2 + 1];
            u64 v2a = 0ULL, v2b = 0ULL;          // two chains for ILP
            v2a = ffma2(a0.x, wa[0], v2a);  v2b = ffma2(a0.y, wa[1], v2b);
            v2a = ffma2(a1.x, wa[2], v2a);  v2b = ffma2(a1.y, wa[3], v2b);
            v2a = ffma2(x0.x, wb[0], v2a);  v2b = ffma2(x0.y, wb[1], v2b);
            v2a = ffma2(x1.x, wb[2], v2a);  v2b = ffma2(x1.y, wb[3], v2b);
            float2 sa = up2(v2a), sb = up2(v2b);
            float v = bj + (sa.x + sa.y) + (sb.x + sb.y);
            shf[n * F1 + j] = fmaxf(v, 0.f);
        }
    }
    __syncthreads();

    // ---- conv2 aggregation: one thread per (node, float4-quarter), FFMA2 ----
    for (int it = tid; it < NPG * 4; it += 128) {
        int n = it >> 2, q = it & 3;
        u64 acc0 = 0ULL, acc1 = 0ULL;
        int k1 = soff[n + 1];
        for (int k = soff[n]; k < k1; k++) {
            float2 e = sedge[k];
            u64 es = pk2(e.x, e.x);
            ulonglong2 hv = *(const ulonglong2*)&sh4[__float_as_int(e.y) * 4 + q];
            acc0 = ffma2(es, hv.x, acc0);
            acc1 = ffma2(es, hv.y, acc1);
        }
        float2 a01 = up2(acc0), a23 = up2(acc1);
        sagg4[it] = make_float4(a01.x, a01.y, a23.x, a23.y);    // layout [n][4]
    }
    __syncthreads();

    // ---- conv2 linear + ReLU, input-pair FFMA2, coalesced STG ----
    {
        const int c = tid & 3, g = tid >> 2;    // g in 0..31
        u64 wa[8], wb[8];
        #pragma unroll
        for (int i2 = 0; i2 < 8; i2++) {
            wa[i2] = pk2(wr2[(2 * i2) * F2 + c],  wr2[(2 * i2 + 1) * F2 + c]);
            wb[i2] = pk2(wrt2[(2 * i2) * F2 + c], wrt2[(2 * i2 + 1) * F2 + c]);
        }
        const float bc = sb2[c];
        for (int n = g; n < NPG; n += 32) {
            u64 v2a = 0ULL, v2b = 0ULL;
            #pragma unroll
            for (int q = 0; q < 4; q++) {
                ulonglong2 a = *(const ulonglong2*)&sagg4[n * 4 + q];
                ulonglong2 h = *(const ulonglong2*)&sh4[n * 4 + q];
                v2a = ffma2(a.x, wa[q * 2], v2a);
                v2b = ffma2(a.y, wa[q * 2 + 1], v2b);
                v2a = ffma2(h.x, wb[q * 2], v2a);
                v2b = ffma2(h.y, wb[q * 2 + 1], v2b);
            }
            float2 sa = up2(v2a), sbv = up2(v2b);
            float v = bc + (sa.x + sa.y) + (sbv.x + sbv.y);
            g_emb[(size_t)b * CAT + n * F2 + c] = fmaxf(v, 0.f);
        }
    }
}

// ---------------------------------------------------------------------------
// Kernel 2: head.  out = sigmoid( relu(concat @ Wo1 + bo1) @ Wo2 + bo2 )
// 64x128 tile, 256 threads, 4x8 microtile via FFMA2 (16 FFMA2/k/thread),
// fused epilogue (hidden layer never hits HBM).
// ---------------------------------------------------------------------------
__global__ void __launch_bounds__(256) head_kernel(
    const float* __restrict__ Wo1, const float* __restrict__ bo1,
    const float* __restrict__ Wo2, const float* __restrict__ bo2,
    float* __restrict__ out)
{
    constexpr int BK = 16;
    __shared__ __align__(16) float  As[BK][BM + 4];   // padded, float4-readable
    __shared__ __align__(16) float4 Bs4[BK][32];      // [BK][128] floats
    __shared__ float  red[BM][17];

    const int rowBase = blockIdx.x * BM;
    const int tid = threadIdx.x;
    const int tx = tid & 15, ty = tid >> 4;           // ty 0..15

    u64 acc2[4][4];                                   // 4 rows x 4 col-pairs
    #pragma unroll
    for (int i = 0; i < 4; i++)
        #pragma unroll
        for (int j = 0; j < 4; j++) acc2[i][j] = 0ULL;

    const float* A = g_emb + (size_t)rowBase * CAT;

    for (int k0 = 0; k0 < CAT; k0 += BK) {
        #pragma unroll
        for (int l = 0; l < 4; l++) {                 // A: 64x16 scalars
            int idx = tid + l * 256;
            int row = idx >> 4, kk = idx & 15;
            int k = k0 + kk;
            As[kk][row] = (k < CAT) ? A[(size_t)row * CAT + k] : 0.f;
        }
        #pragma unroll
        for (int l = 0; l < 2; l++) {                 // B: 16x128 via float4
            int idx = tid + l * 256;
            int kk = idx >> 5, c4 = idx & 31;
            int k = k0 + kk;
            Bs4[kk][c4] = (k < CAT) ? *(const float4*)&Wo1[(size_t)k * H1 + c4 * 4]
                                    : make_float4(0.f, 0.f, 0.f, 0.f);
        }
        __syncthreads();
        #pragma unroll
        for (int kk = 0; kk < BK; kk++) {
            float4 a = *(const float4*)&As[kk][ty * 4];
            u64 as0 = pk2(a.x, a.x), as1 = pk2(a.y, a.y);
            u64 as2 = pk2(a.z, a.z), as3 = pk2(a.w, a.w);
            ulonglong2 bq0 = *(const ulonglong2*)&Bs4[kk][tx * 2];
            ulonglong2 bq1 = *(const ulonglong2*)&Bs4[kk][tx * 2 + 1];
            u64 bp0 = bq0.x, bp1 = bq0.y, bp2 = bq1.x, bp3 = bq1.y;
            acc2[0][0] = ffma2(as0, bp0, acc2[0][0]);
            acc2[0][1] = ffma2(as0, bp1, acc2[0][1]);
            acc2[0][2] = ffma2(as0, bp2, acc2[0][2]);
            acc2[0][3] = ffma2(as0, bp3, acc2[0][3]);
            acc2[1][0] = ffma2(as1, bp0, acc2[1][0]);
            acc2[1][1] = ffma2(as1, bp1, acc2[1][1]);
            acc2[1][2] = ffma2(as1, bp2, acc2[1][2]);
            acc2[1][3] = ffma2(as1, bp3, acc2[1][3]);
            acc2[2][0] = ffma2(as2, bp0, acc2[2][0]);
            acc2[2][1] = ffma2(as2, bp1, acc2[2][1]);
            acc2[2][2] = ffma2(as2, bp2, acc2[2][2]);
            acc2[2][3] = ffma2(as2, bp3, acc2[2][3]);
            acc2[3][0] = ffma2(as3, bp0, acc2[3][0]);
            acc2[3][1] = ffma2(as3, bp1, acc2[3][1]);
            acc2[3][2] = ffma2(as3, bp2, acc2[3][2]);
            acc2[3][3] = ffma2(as3, bp3, acc2[3][3]);
        }
        __syncthreads();
    }

    // epilogue: bias + relu + dot(Wo2) partials, then cross-column reduce
    float bb[8], w2[8];
    #pragma unroll
    for (int j = 0; j < 8; j++) { bb[j] = bo1[tx * 8 + j]; w2[j] = Wo2[tx * 8 + j]; }
    #pragma unroll
    for (int i = 0; i < 4; i++) {
        float p = 0.f;
        #pragma unroll
        for (int jp = 0; jp < 4; jp++) {
            float2 v = up2(acc2[i][jp]);
            float v0 = fmaxf(v.x + bb[jp * 2], 0.f);
            float v1 = fmaxf(v.y + bb[jp * 2 + 1], 0.f);
            p += v0 * w2[jp * 2] + v1 * w2[jp * 2 + 1];
        }
        red[ty * 4 + i][tx] = p;
    }
    __syncthreads();
    if (tid < BM) {
        float s = bo2[0];
        #pragma unroll
        for (int t = 0; t < 16; t++) s += red[tid][t];
        out[rowBase + tid] = 1.f / (1.f + expf(-s));
    }
}

extern "C" void kernel_launch(void* const* d_in, const int* in_sizes, int n_in,
                              void* d_out, int out_size)
{
    const float* x       = (const float*)d_in[0];
    const int*   eidx    = (const int*)  d_in[1];
    const float* eattr   = (const float*)d_in[2];
    const float* gfeat   = (const float*)d_in[3];
    const float* W_rel1  = (const float*)d_in[4];
    const float* b1      = (const float*)d_in[5];
    const float* W_root1 = (const float*)d_in[6];
    const float* W_rel2  = (const float*)d_in[7];
    const float* b2      = (const float*)d_in[8];
    const float* W_root2 = (const float*)d_in[9];
    const float* Wg1     = (const float*)d_in[10];
    const float* bg1     = (const float*)d_in[11];
    const float* Wg2     = (const float*)d_in[12];
    const float* bg2     = (const float*)d_in[13];
    const float* Wg3     = (const float*)d_in[14];
    const float* bg3     = (const float*)d_in[15];
    const float* Wo1     = (const float*)d_in[16];
    const float* bo1     = (const float*)d_in[17];
    const float* Wo2     = (const float*)d_in[18];
    const float* bo2     = (const float*)d_in[19];
    float* out = (float*)d_out;

    gconv_kernel<<<BGR, 128>>>(x, eidx, eattr, gfeat,
                               W_rel1, b1, W_root1,
                               W_rel2, b2, W_root2,
                               Wg1, bg1, Wg2, bg2, Wg3, bg3);
    head_kernel<<<BGR / BM, 256>>>(Wo1, bo1, Wo2, bo2, out);
}

// round 10
// speedup vs baseline: 1.8047x; 1.8047x over previous
#include <cuda_runtime.h>
#include <math.h>

#define BGR 32768
#define NPG 54
#define EPG 144
#define GLOB 10
#define F0 8
#define F1 16
#define F2 4
#define CAT 226   /* 54*4 + 10 */
#define H1 128
#define BM 64

// Scratch: concat([embeds, g]) per graph, [B, 226]
__device__ float g_emb[BGR * CAT];

// ---------------------------------------------------------------------------
// Kernel 1: per-graph GraphConv x2 (+ ReLU) and the global-feature MLP.
// TWO graphs per CTA (256 threads; sub = tid>>7 selects the graph) to halve
// per-graph fixed costs (weight loads, barriers, CTA setup). Counting-sort
// CSR built once per graph, reused by both conv layers. All feature traffic
// float4; sorted edges packed {attr, src} float2; weights in registers for
// the linear layers.
// ---------------------------------------------------------------------------
__global__ void __launch_bounds__(256) gconv_kernel(
    const float* __restrict__ x,
    const int*   __restrict__ eidx,    // [2, E]
    const float* __restrict__ eattr,
    const float* __restrict__ gfeat,
    const float* __restrict__ W_rel1, const float* __restrict__ b1,
    const float* __restrict__ W_root1,
    const float* __restrict__ W_rel2, const float* __restrict__ b2,
    const float* __restrict__ W_root2,
    const float* __restrict__ Wg1, const float* __restrict__ bg1,
    const float* __restrict__ Wg2, const float* __restrict__ bg2,
    const float* __restrict__ Wg3, const float* __restrict__ bg3)
{
    const int tid = threadIdx.x;
    const int sub = tid >> 7;          // which of the 2 graphs
    const int lt  = tid & 127;         // lane within the graph's 128 threads
    const int b   = blockIdx.x * 2 + sub;

    __shared__ float4 sx4[2][NPG * 2];     // x        [54][8]  as float4 pairs
    __shared__ float4 sh4[2][NPG * 4];     // conv1 out [54][16]
    __shared__ float4 sagg4[2][NPG * 4];   // agg scratch (aliased early)
    __shared__ float2 sedge[2][EPG];       // dst-sorted {attr, src_as_float}
    __shared__ int    soff[2][NPG + 1];
    __shared__ int    scur[2][NPG];
    __shared__ int    wsum0[2];
    __shared__ float  wr1[F0 * F1], wrt1[F0 * F1], sb1[F1];
    __shared__ float  wr2[F1 * F2], wrt2[F1 * F2], sb2[F2];
    __shared__ float  wg1[GLOB * 8], wg2[64], wg3[80];
    __shared__ float  sbg1[8], sbg2[8], sbg3[GLOB];
    __shared__ float  sgf[2][GLOB], sg1[2][8], sg2[2][8];

    // unsorted edge staging aliases this graph's sagg4 (dead until after scatter)
    float* sattr_u = (float*)sagg4[sub];       // [144]
    short* ssrc_u  = (short*)(sattr_u + EPG);  // [144]
    short* sdst_u  = ssrc_u + EPG;             // [144]
    float* shf     = (float*)sh4[sub];

    // ---- loads ----
    {
        const float4* xg = (const float4*)(x + (size_t)b * (NPG * F0));
        if (lt < NPG * 2) sx4[sub][lt] = xg[lt];
    }
    {
        const int*   srcg = eidx + (size_t)b * EPG;
        const int*   dstg = eidx + (size_t)BGR * EPG + (size_t)b * EPG;
        const float* ag   = eattr + (size_t)b * EPG;
        const int base = b * NPG;
        for (int e = lt; e < EPG; e += 128) {
            ssrc_u[e]  = (short)(srcg[e] - base);
            sdst_u[e]  = (short)(dstg[e] - base);
            sattr_u[e] = ag[e];
        }
    }
    // weights: one copy, loaded by the whole CTA
    if (tid < F0 * F1) { wr1[tid] = W_rel1[tid]; wrt1[tid] = W_root1[tid]; }
    if (tid >= 128 && tid < 128 + F1 * F2) {
        int i = tid - 128; wr2[i] = W_rel2[i]; wrt2[i] = W_root2[i];
    }
    if (tid >= 192 && tid < 192 + F1) sb1[tid - 192] = b1[tid - 192];
    if (tid >= 208 && tid < 208 + F2) sb2[tid - 208] = b2[tid - 208];
    if (tid < GLOB * 8) wg1[tid] = Wg1[tid];
    if (tid >= 80 && tid < 144) wg2[tid - 80] = Wg2[tid - 80];
    if (tid >= 144 && tid < 224) wg3[tid - 144] = Wg3[tid - 144];
    if (tid >= 224 && tid < 232) sbg1[tid - 224] = bg1[tid - 224];
    if (tid >= 232 && tid < 240) sbg2[tid - 232] = bg2[tid - 232];
    if (tid >= 240 && tid < 250) sbg3[tid - 240] = bg3[tid - 240];
    if (lt < GLOB) sgf[sub][lt] = gfeat[(size_t)b * GLOB + lt];
    if (lt < NPG) scur[sub][lt] = 0;
    __syncthreads();

    // ---- degree counts (+ global-MLP layer 1) ----
    for (int e = lt; e < EPG; e += 128) atomicAdd(&scur[sub][sdst_u[e]], 1);
    if (lt < 8) {
        float v = sbg1[lt];
        #pragma unroll
        for (int i = 0; i < GLOB; i++) v += sgf[sub][i] * wg1[i * 8 + lt];
        sg1[sub][lt] = fmaxf(v, 0.f);
    }
    __syncthreads();

    // ---- warp-shuffle prefix scan over 54 counts (2 warps per graph) ----
    if (lt < 64) {
        int c = (lt < NPG) ? scur[sub][lt] : 0;
        int lane = lt & 31;
        int v = c;
        #pragma unroll
        for (int o = 1; o < 32; o <<= 1) {
            int u = __shfl_up_sync(0xffffffffu, v, o);
            if (lane >= o) v += u;
        }
        if (lt < NPG) soff[sub][lt + 1] = v;
        if (lt == 31) wsum0[sub] = v;
        if (lt == 0)  soff[sub][0] = 0;
    }
    if (lt >= 64 && lt < 72) {     // global-MLP layer 2 on the third warp
        int j = lt - 64;
        float v = sbg2[j];
        #pragma unroll
        for (int i = 0; i < 8; i++) v += sg1[sub][i] * wg2[i * 8 + j];
        sg2[sub][j] = fmaxf(v, 0.f);
    }
    __syncthreads();
    if (lt >= 32 && lt < NPG) soff[sub][lt + 1] += wsum0[sub];
    __syncthreads();
    if (lt < NPG) scur[sub][lt] = soff[sub][lt];
    __syncthreads();

    // ---- scatter edges into CSR slots (+ global-MLP layer 3 writeout) ----
    for (int e = lt; e < EPG; e += 128) {
        int slot = atomicAdd(&scur[sub][sdst_u[e]], 1);
        float2 pe; pe.x = sattr_u[e]; pe.y = __int_as_float((int)ssrc_u[e]);
        sedge[sub][slot] = pe;
    }
    if (lt < GLOB) {
        float v = sbg3[lt];
        #pragma unroll
        for (int i = 0; i < 8; i++) v += sg2[sub][i] * wg3[i * GLOB + lt];
        g_emb[(size_t)b * CAT + NPG * F2 + lt] = fmaxf(v, 0.f);
    }
    __syncthreads();   // staging alias dead after this -> sagg4 reusable

    // ---- conv1 aggregation: one thread per (node, float4-half) ----
    if (lt < NPG * 2) {
        int n = lt >> 1, h = lt & 1;
        float4 a = make_float4(0.f, 0.f, 0.f, 0.f);
        int k1 = soff[sub][n + 1];
        for (int k = soff[sub][n]; k < k1; k++) {
            float2 e = sedge[sub][k];
            float4 xv = sx4[sub][__float_as_int(e.y) * 2 + h];
            a.x += e.x * xv.x; a.y += e.x * xv.y;
            a.z += e.x * xv.z; a.w += e.x * xv.w;
        }
        sagg4[sub][lt] = a;    // layout [n][2]
    }
    __syncthreads();

    // ---- conv1 linear + ReLU: weights in regs, one column per thread ----
    {
        const int j = lt & 15, g = lt >> 4;   // g in 0..7
        float wc[16];
        const float bj = sb1[j];
        #pragma unroll
        for (int i = 0; i < F0; i++) { wc[i] = wr1[i * F1 + j]; wc[8 + i] = wrt1[i * F1 + j]; }
        for (int n = g; n < NPG; n += 8) {
            float4 a0 = sagg4[sub][n * 2], a1 = sagg4[sub][n * 2 + 1];
            float4 x0 = sx4[sub][n * 2],  x1 = sx4[sub][n * 2 + 1];
            float v = bj;
            v += a0.x * wc[0] + a0.y * wc[1] + a0.z * wc[2] + a0.w * wc[3];
            v += a1.x * wc[4] + a1.y * wc[5] + a1.z * wc[6] + a1.w * wc[7];
            v += x0.x * wc[8] + x0.y * wc[9] + x0.z * wc[10] + x0.w * wc[11];
            v += x1.x * wc[12] + x1.y * wc[13] + x1.z * wc[14] + x1.w * wc[15];
            shf[n * F1 + j] = fmaxf(v, 0.f);
        }
    }
    __syncthreads();

    // ---- conv2 aggregation: one thread per (node, float4-quarter) ----
    for (int it = lt; it < NPG * 4; it += 128) {
        int n = it >> 2, q = it & 3;
        float4 a = make_float4(0.f, 0.f, 0.f, 0.f);
        int k1 = soff[sub][n + 1];
        for (int k = soff[sub][n]; k < k1; k++) {
            float2 e = sedge[sub][k];
            float4 hv = sh4[sub][__float_as_int(e.y) * 4 + q];
            a.x += e.x * hv.x; a.y += e.x * hv.y;
            a.z += e.x * hv.z; a.w += e.x * hv.w;
        }
        sagg4[sub][it] = a;     // layout [n][4]
    }
    __syncthreads();

    // ---- conv2 linear + ReLU, write embeds (coalesced STG) ----
    {
        const int c = lt & 3, g = lt >> 2;    // g in 0..31
        float wa[16], wb[16];
        #pragma unroll
        for (int j = 0; j < F1; j++) { wa[j] = wr2[j * F2 + c]; wb[j] = wrt2[j * F2 + c]; }
        const float bc = sb2[c];
        for (int n = g; n < NPG; n += 32) {
            float v = bc;
            #pragma unroll
            for (int q = 0; q < 4; q++) {
                float4 a = sagg4[sub][n * 4 + q];
                float4 h = sh4[sub][n * 4 + q];
                v += a.x * wa[q * 4 + 0] + a.y * wa[q * 4 + 1]
                   + a.z * wa[q * 4 + 2] + a.w * wa[q * 4 + 3];
                v += h.x * wb[q * 4 + 0] + h.y * wb[q * 4 + 1]
                   + h.z * wb[q * 4 + 2] + h.w * wb[q * 4 + 3];
            }
            g_emb[(size_t)b * CAT + n * F2 + c] = fmaxf(v, 0.f);
        }
    }
}

// ---------------------------------------------------------------------------
// Kernel 2: head.  out = sigmoid( relu(concat @ Wo1 + bo1) @ Wo2 + bo2 )
// 64x128 tile, 128 threads, 8x8 microtile (64 FMA vs 4 LDS.128 per k-step:
// smem-crossbar balanced), fused epilogue (hidden layer never hits HBM).
// ---------------------------------------------------------------------------
__global__ void __launch_bounds__(128) head_kernel(
    const float* __restrict__ Wo1, const float* __restrict__ bo1,
    const float* __restrict__ Wo2, const float* __restrict__ bo2,
    float* __restrict__ out)
{
    constexpr int BK = 16;
    __shared__ __align__(16) float  As[BK][BM + 4];   // padded, float4-readable
    __shared__ __align__(16) float4 Bs4[BK][32];      // [BK][128] floats
    __shared__ float  red[BM][17];

    const int rowBase = blockIdx.x * BM;
    const int tid = threadIdx.x;
    const int tx = tid & 15, ty = tid >> 4;           // ty 0..7

    float acc[8][8];
    #pragma unroll
    for (int i = 0; i < 8; i++)
        #pragma unroll
        for (int j = 0; j < 8; j++) acc[i][j] = 0.f;

    const float* A = g_emb + (size_t)rowBase * CAT;

    for (int k0 = 0; k0 < CAT; k0 += BK) {
        #pragma unroll
        for (int l = 0; l < 8; l++) {                 // A: 64x16 scalars
            int idx = tid + l * 128;
            int row = idx >> 4, kk = idx & 15;
            int k = k0 + kk;
            As[kk][row] = (k < CAT) ? A[(size_t)row * CAT + k] : 0.f;
        }
        #pragma unroll
        for (int l = 0; l < 4; l++) {                 // B: 16x128 via float4
            int idx = tid + l * 128;
            int kk = idx >> 5, c4 = idx & 31;
            int k = k0 + kk;
            Bs4[kk][c4] = (k < CAT) ? *(const float4*)&Wo1[(size_t)k * H1 + c4 * 4]
                                    : make_float4(0.f, 0.f, 0.f, 0.f);
        }
        __syncthreads();
        #pragma unroll
        for (int kk = 0; kk < BK; kk++) {
            float4 a0 = *(const float4*)&As[kk][ty * 8];
            float4 a1 = *(const float4*)&As[kk][ty * 8 + 4];
            float4 b0 = Bs4[kk][tx * 2];
            float4 b1 = Bs4[kk][tx * 2 + 1];
            float av[8] = {a0.x, a0.y, a0.z, a0.w, a1.x, a1.y, a1.z, a1.w};
            float bv[8] = {b0.x, b0.y, b0.z, b0.w, b1.x, b1.y, b1.z, b1.w};
            #pragma unroll
            for (int i = 0; i < 8; i++)
                #pragma unroll
                for (int j = 0; j < 8; j++)
                    acc[i][j] += av[i] * bv[j];
        }
        __syncthreads();
    }

    // epilogue: bias + relu + dot(Wo2) partials, then cross-column reduce
    float bb[8], w2[8];
    #pragma unroll
    for (int j = 0; j < 8; j++) { bb[j] = bo1[tx * 8 + j]; w2[j] = Wo2[tx * 8 + j]; }
    #pragma unroll
    for (int i = 0; i < 8; i++) {
        float p = 0.f;
        #pragma unroll
        for (int j = 0; j < 8; j++) {
            float v = fmaxf(acc[i][j] + bb[j], 0.f);
            p += v * w2[j];
        }
        red[ty * 8 + i][tx] = p;
    }
    __syncthreads();
    if (tid < BM) {
        float s = bo2[0];
        #pragma unroll
        for (int t = 0; t < 16; t++) s += red[tid][t];
        out[rowBase + tid] = 1.f / (1.f + expf(-s));
    }
}

extern "C" void kernel_launch(void* const* d_in, const int* in_sizes, int n_in,
                              void* d_out, int out_size)
{
    const float* x       = (const float*)d_in[0];
    const int*   eidx    = (const int*)  d_in[1];
    const float* eattr   = (const float*)d_in[2];
    const float* gfeat   = (const float*)d_in[3];
    const float* W_rel1  = (const float*)d_in[4];
    const float* b1      = (const float*)d_in[5];
    const float* W_root1 = (const float*)d_in[6];
    const float* W_rel2  = (const float*)d_in[7];
    const float* b2      = (const float*)d_in[8];
    const float* W_root2 = (const float*)d_in[9];
    const float* Wg1     = (const float*)d_in[10];
    const float* bg1     = (const float*)d_in[11];
    const float* Wg2     = (const float*)d_in[12];
    const float* bg2     = (const float*)d_in[13];
    const float* Wg3     = (const float*)d_in[14];
    const float* bg3     = (const float*)d_in[15];
    const float* Wo1     = (const float*)d_in[16];
    const float* bo1     = (const float*)d_in[17];
    const float* Wo2     = (const float*)d_in[18];
    const float* bo2     = (const float*)d_in[19];
    float* out = (float*)d_out;

    gconv_kernel<<<BGR / 2, 256>>>(x, eidx, eattr, gfeat,
                                   W_rel1, b1, W_root1,
                                   W_rel2, b2, W_root2,
                                   Wg1, bg1, Wg2, bg2, Wg3, bg3);
    head_kernel<<<BGR / BM, 128>>>(Wo1, bo1, Wo2, bo2, out);
}